// round 7
// baseline (speedup 1.0000x reference)
#include <cuda_runtime.h>
#include <cstdint>

#define N_NODES 100000
#define N_EDGES 20000
#define NNZ     800000
#define D       128

// Scan tiling
#define SCAN_TPB   256
#define SCAN_PER   8
#define SCAN_CHUNK (SCAN_TPB * SCAN_PER)                      // 2048
#define NB1 ((N_EDGES + SCAN_CHUNK - 1) / SCAN_CHUNK)         // 10
#define NB2 ((N_NODES + SCAN_CHUNK - 1) / SCAN_CHUNK)         // 49
#define NBT (NB1 + NB2)                                       // 59

// ---------------------------------------------------------------------------
// Device-global scratch (allocation-free rule)
// ---------------------------------------------------------------------------
__device__ __align__(16) float g_Xe[N_EDGES * D];    // 10.24 MB (pre-scaled by degE)
__device__ __align__(16) float g_Xv[N_NODES * D];    // 51.2 MB (Xi)
__device__ __align__(16) float2 g_Wp[64 * 128];      // packed tf32 B fragments, 64 KB

__device__ int g1_cnt[N_EDGES];
__device__ int g1_off[N_EDGES + 1];
__device__ int g1_cur[N_EDGES];
__device__ int g1_idx[NNZ];
__device__ int g2_cnt[N_NODES];
__device__ int g2_off[N_NODES + 1];
__device__ int g2_cur[N_NODES];
__device__ int g2_idx[NNZ];

__device__ int g_thr_excl[NBT * SCAN_TPB];
__device__ int g_blk_sum[NBT];

// ---------------------------------------------------------------------------
// tf32 helper
// ---------------------------------------------------------------------------
__device__ __forceinline__ uint32_t f2tf32(float f) {
    uint32_t r;
    asm("cvt.rna.tf32.f32 %0, %1;" : "=r"(r) : "f"(f));
    return r;
}

// ---------------------------------------------------------------------------
// Per-graph zero kernels (g2's merged with W prep — both on side stream)
// ---------------------------------------------------------------------------
__global__ void zero_g1_kernel() {
    int i = blockIdx.x * blockDim.x + threadIdx.x;
    if (i < N_EDGES) g1_cnt[i] = 0;
}

#define ZERO2_BLKS ((N_NODES + 255) / 256)        // 391
#define WPREP_BLKS 32

__global__ void zero_g2_wprep_kernel(const float* __restrict__ W) {
    if (blockIdx.x < ZERO2_BLKS) {
        int i = blockIdx.x * blockDim.x + threadIdx.x;
        if (i < N_NODES) g2_cnt[i] = 0;
    } else {
        int p = (blockIdx.x - ZERO2_BLKS) * blockDim.x + threadIdx.x;  // 8192
        if (p < 64 * 128) {
            int n = p & 127;
            int tig = (p >> 7) & 3;
            int kk = p >> 9;
            float w0 = __ldg(W + n * 128 + kk * 8 + tig);
            float w1 = __ldg(W + n * 128 + kk * 8 + tig + 4);
            float2 o;
            o.x = __uint_as_float(f2tf32(w0));
            o.y = __uint_as_float(f2tf32(w1));
            g_Wp[p] = o;
        }
    }
}

// ---------------------------------------------------------------------------
// Per-graph histogram (int4-vectorized: 4 nnz per thread)
// ---------------------------------------------------------------------------
__global__ void hist_g_kernel(const int4* __restrict__ dst4, int graph) {
    int i = blockIdx.x * blockDim.x + threadIdx.x;
    if (i >= NNZ / 4) return;
    int4 d = __ldg(dst4 + i);
    int* cnt = graph ? g2_cnt : g1_cnt;
    atomicAdd(&cnt[d.x], 1);
    atomicAdd(&cnt[d.y], 1);
    atomicAdd(&cnt[d.z], 1);
    atomicAdd(&cnt[d.w], 1);
}

// ---------------------------------------------------------------------------
// Phase A: per-block partial scan (per graph)
// ---------------------------------------------------------------------------
__global__ void scanA_g_kernel(int graph) {
    const int bid = blockIdx.x;
    const int t = threadIdx.x;
    const int* cnt = graph ? g2_cnt : g1_cnt;
    const int n    = graph ? N_NODES : N_EDGES;
    const int slot = (graph ? NB1 : 0) + bid;
    const int lbase = bid * SCAN_CHUNK;

    int s = 0;
    const int i0 = lbase + t * SCAN_PER;
#pragma unroll
    for (int k = 0; k < SCAN_PER; k++) {
        int i = i0 + k;
        s += (i < n) ? cnt[i] : 0;
    }

    const int lane = t & 31, wid = t >> 5;
    int v = s;
#pragma unroll
    for (int o = 1; o < 32; o <<= 1) {
        int u = __shfl_up_sync(0xffffffffu, v, o);
        if (lane >= o) v += u;
    }
    __shared__ int ws[8];
    if (lane == 31) ws[wid] = v;
    __syncthreads();
    if (t < 8) {
        int w = ws[t];
#pragma unroll
        for (int o = 1; o < 8; o <<= 1) {
            int u = __shfl_up_sync(0xffu, w, o);
            if (t >= o) w += u;
        }
        ws[t] = w;
    }
    __syncthreads();

    int excl = v - s + (wid ? ws[wid - 1] : 0);
    g_thr_excl[slot * SCAN_TPB + t] = excl;
    if (t == SCAN_TPB - 1) g_blk_sum[slot] = excl + s;
}

// ---------------------------------------------------------------------------
// Phase C (fused B): every block redundantly scans its graph's block sums.
// ---------------------------------------------------------------------------
__global__ void scanC_g_kernel(int graph) {
    __shared__ int be[64];
    __shared__ int w0tot;
    const int bid = blockIdx.x;
    const int t = threadIdx.x;
    const int nb   = graph ? NB2 : NB1;
    const int gofs = graph ? NB1 : 0;

    if (t < 64) {
        int v = (t < nb) ? g_blk_sum[gofs + t] : 0;
        const int lane = t & 31;
        int s = v;
#pragma unroll
        for (int o = 1; o < 32; o <<= 1) {
            int u = __shfl_up_sync(0xffffffffu, s, o);
            if (lane >= o) s += u;
        }
        if (t == 31) w0tot = s;
        be[t] = s - v;          // warp-local exclusive
    }
    __syncthreads();
    if (t >= 32 && t < 64) be[t] += w0tot;
    __syncthreads();

    const int* cnt; int* off; int* cur; int n;
    if (graph) { cnt = g2_cnt; off = g2_off; cur = g2_cur; n = N_NODES; }
    else       { cnt = g1_cnt; off = g1_off; cur = g1_cur; n = N_EDGES; }
    const int lbase = bid * SCAN_CHUNK;

    int base = be[bid] + g_thr_excl[(gofs + bid) * SCAN_TPB + t];
    const int i0 = lbase + t * SCAN_PER;
#pragma unroll
    for (int k = 0; k < SCAN_PER; k++) {
        int i = i0 + k;
        if (i < n) {
            off[i] = base;
            cur[i] = base;
            base += cnt[i];
        }
    }
    if (bid == 0 && t == 0) off[n] = NNZ;
}

// ---------------------------------------------------------------------------
// Per-graph fill (int2-vectorized: 2 nnz per thread)
// ---------------------------------------------------------------------------
__global__ void fill_g_kernel(const int2* __restrict__ src2,
                              const int2* __restrict__ dst2, int graph) {
    int i = blockIdx.x * blockDim.x + threadIdx.x;
    if (i >= NNZ / 2) return;
    int2 s = __ldg(src2 + i);
    int2 d = __ldg(dst2 + i);
    int* cur = graph ? g2_cur : g1_cur;
    int* idx = graph ? g2_idx : g1_idx;
    int p0 = atomicAdd(&cur[d.x], 1);
    idx[p0] = s.x;
    int p1 = atomicAdd(&cur[d.y], 1);
    idx[p1] = s.y;
}

// ---------------------------------------------------------------------------
// SpMM 1: Xe[e] = degE[e] * sum_{s in csr1[e]} X[s]     (warp per edge)
// ---------------------------------------------------------------------------
__global__ void spmm1_kernel(const float4* __restrict__ X4,
                             const float* __restrict__ degE) {
    int e = (blockIdx.x * blockDim.x + threadIdx.x) >> 5;
    if (e >= N_EDGES) return;
    int lane = threadIdx.x & 31;
    int beg = g1_off[e], end = g1_off[e + 1];

    float4 acc = make_float4(0.f, 0.f, 0.f, 0.f);
    int j = beg;
    for (; j + 4 <= end; j += 4) {
        int s0 = g1_idx[j], s1 = g1_idx[j + 1], s2 = g1_idx[j + 2], s3 = g1_idx[j + 3];
        float4 v0 = __ldg(X4 + s0 * 32 + lane);
        float4 v1 = __ldg(X4 + s1 * 32 + lane);
        float4 v2 = __ldg(X4 + s2 * 32 + lane);
        float4 v3 = __ldg(X4 + s3 * 32 + lane);
        acc.x += (v0.x + v1.x) + (v2.x + v3.x);
        acc.y += (v0.y + v1.y) + (v2.y + v3.y);
        acc.z += (v0.z + v1.z) + (v2.z + v3.z);
        acc.w += (v0.w + v1.w) + (v2.w + v3.w);
    }
    for (; j < end; j++) {
        int s = g1_idx[j];
        float4 v = __ldg(X4 + s * 32 + lane);
        acc.x += v.x; acc.y += v.y; acc.z += v.z; acc.w += v.w;
    }
    float de = __ldg(degE + e);
    acc.x *= de; acc.y *= de; acc.z *= de; acc.w *= de;
    reinterpret_cast<float4*>(g_Xe)[e * 32 + lane] = acc;
}

// ---------------------------------------------------------------------------
// SpMM 2 + residual: g_Xv[v] = (1-a)*degV[v]*sum_{s in csr2[v]} Xe[s] + a*X0[v]
// ---------------------------------------------------------------------------
__global__ void spmm2_kernel(const float4* __restrict__ X04,
                             const float* __restrict__ degV,
                             const float* __restrict__ alpha) {
    int v = (blockIdx.x * blockDim.x + threadIdx.x) >> 5;
    if (v >= N_NODES) return;
    int lane = threadIdx.x & 31;
    int beg = g2_off[v], end = g2_off[v + 1];

    const float4* Xe4 = reinterpret_cast<const float4*>(g_Xe);
    float4 acc = make_float4(0.f, 0.f, 0.f, 0.f);
    int j = beg;
    for (; j + 4 <= end; j += 4) {
        int s0 = g2_idx[j], s1 = g2_idx[j + 1], s2 = g2_idx[j + 2], s3 = g2_idx[j + 3];
        float4 v0 = Xe4[s0 * 32 + lane];
        float4 v1 = Xe4[s1 * 32 + lane];
        float4 v2 = Xe4[s2 * 32 + lane];
        float4 v3 = Xe4[s3 * 32 + lane];
        acc.x += (v0.x + v1.x) + (v2.x + v3.x);
        acc.y += (v0.y + v1.y) + (v2.y + v3.y);
        acc.z += (v0.z + v1.z) + (v2.z + v3.z);
        acc.w += (v0.w + v1.w) + (v2.w + v3.w);
    }
    for (; j < end; j++) {
        int s = g2_idx[j];
        float4 w = Xe4[s * 32 + lane];
        acc.x += w.x; acc.y += w.y; acc.z += w.z; acc.w += w.w;
    }
    float a = __ldg(alpha);
    float sc = (1.f - a) * __ldg(degV + v);
    float4 x0 = __ldg(X04 + v * 32 + lane);
    float4 xi;
    xi.x = sc * acc.x + a * x0.x;
    xi.y = sc * acc.y + a * x0.y;
    xi.z = sc * acc.z + a * x0.z;
    xi.w = sc * acc.w + a * x0.w;
    reinterpret_cast<float4*>(g_Xv)[v * 32 + lane] = xi;
}

// ---------------------------------------------------------------------------
// GEMM: out = (1-b)*Xi + b*(Xi @ W^T)   (Xi in g_Xv; exact 16-row tiling)
// ---------------------------------------------------------------------------
#define XI_STRIDE 132

__global__ void __launch_bounds__(256, 2)
gemm_kernel(const float* __restrict__ beta, float* __restrict__ out) {
    __shared__ float Xism[16 * XI_STRIDE];

    const int tid = threadIdx.x;
    const int row0 = blockIdx.x * 16;
    const float bb = __ldg(beta);
    const float omb = 1.f - bb;

    const int warp = tid >> 5, lane = tid & 31;
    const int gid = lane >> 2, tig = lane & 3;
    const int nt0 = warp, nt1 = warp + 8;

    float2 bf0[16], bf1[16];
#pragma unroll
    for (int kk = 0; kk < 16; kk++) {
        bf0[kk] = __ldg(&g_Wp[(kk * 4 + tig) * 128 + nt0 * 8 + gid]);
        bf1[kk] = __ldg(&g_Wp[(kk * 4 + tig) * 128 + nt1 * 8 + gid]);
    }

    const float4* Xv4 = reinterpret_cast<const float4*>(g_Xv);
#pragma unroll
    for (int i = tid; i < 16 * 32; i += 256) {
        int r = i >> 5, c4 = i & 31;
        float4 xi = Xv4[(row0 + r) * 32 + c4];
        *reinterpret_cast<float4*>(&Xism[r * XI_STRIDE + c4 * 4]) = xi;
    }
    __syncthreads();

    float c00 = 0.f, c01 = 0.f, c02 = 0.f, c03 = 0.f;
    float c10 = 0.f, c11 = 0.f, c12 = 0.f, c13 = 0.f;

#pragma unroll
    for (int kk = 0; kk < 16; kk++) {
        int c = kk * 8 + tig;
        uint32_t a0 = f2tf32(Xism[gid * XI_STRIDE + c]);
        uint32_t a1 = f2tf32(Xism[(gid + 8) * XI_STRIDE + c]);
        uint32_t a2 = f2tf32(Xism[gid * XI_STRIDE + c + 4]);
        uint32_t a3 = f2tf32(Xism[(gid + 8) * XI_STRIDE + c + 4]);
        uint32_t b00 = __float_as_uint(bf0[kk].x);
        uint32_t b01 = __float_as_uint(bf0[kk].y);
        uint32_t b10 = __float_as_uint(bf1[kk].x);
        uint32_t b11 = __float_as_uint(bf1[kk].y);
        asm volatile(
            "mma.sync.aligned.m16n8k8.row.col.f32.tf32.tf32.f32 "
            "{%0,%1,%2,%3}, {%4,%5,%6,%7}, {%8,%9}, {%0,%1,%2,%3};"
            : "+f"(c00), "+f"(c01), "+f"(c02), "+f"(c03)
            : "r"(a0), "r"(a1), "r"(a2), "r"(a3), "r"(b00), "r"(b01));
        asm volatile(
            "mma.sync.aligned.m16n8k8.row.col.f32.tf32.tf32.f32 "
            "{%0,%1,%2,%3}, {%4,%5,%6,%7}, {%8,%9}, {%0,%1,%2,%3};"
            : "+f"(c10), "+f"(c11), "+f"(c12), "+f"(c13)
            : "r"(a0), "r"(a1), "r"(a2), "r"(a3), "r"(b10), "r"(b11));
    }

    const int r0 = row0 + gid;
    const int r1 = r0 + 8;
    {
        int col = nt0 * 8 + 2 * tig;
        float xi0 = Xism[gid * XI_STRIDE + col];
        float xi1 = Xism[gid * XI_STRIDE + col + 1];
        *reinterpret_cast<float2*>(out + (long)r0 * 128 + col) =
            make_float2(omb * xi0 + bb * c00, omb * xi1 + bb * c01);
        xi0 = Xism[(gid + 8) * XI_STRIDE + col];
        xi1 = Xism[(gid + 8) * XI_STRIDE + col + 1];
        *reinterpret_cast<float2*>(out + (long)r1 * 128 + col) =
            make_float2(omb * xi0 + bb * c02, omb * xi1 + bb * c03);

        col = nt1 * 8 + 2 * tig;
        xi0 = Xism[gid * XI_STRIDE + col];
        xi1 = Xism[gid * XI_STRIDE + col + 1];
        *reinterpret_cast<float2*>(out + (long)r0 * 128 + col) =
            make_float2(omb * xi0 + bb * c10, omb * xi1 + bb * c11);
        xi0 = Xism[(gid + 8) * XI_STRIDE + col];
        xi1 = Xism[(gid + 8) * XI_STRIDE + col + 1];
        *reinterpret_cast<float2*>(out + (long)r1 * 128 + col) =
            make_float2(omb * xi0 + bb * c12, omb * xi1 + bb * c13);
    }
}

// ---------------------------------------------------------------------------
// kernel_launch — two-stream fork/join (g2 CSR build overlaps g1 chain+spmm1)
// ---------------------------------------------------------------------------
extern "C" void kernel_launch(void* const* d_in, const int* in_sizes, int n_in,
                              void* d_out, int out_size) {
    const float* X     = (const float*)d_in[0];
    const float* X0    = (const float*)d_in[1];
    const float* degE  = (const float*)d_in[2];
    const float* degV  = (const float*)d_in[3];
    const float* alpha = (const float*)d_in[4];
    const float* beta  = (const float*)d_in[5];
    const float* W     = (const float*)d_in[6];
    const int*   g1s   = (const int*)d_in[7];
    const int*   g1d   = (const int*)d_in[8];
    const int*   g2s   = (const int*)d_in[9];
    const int*   g2d   = (const int*)d_in[10];
    float* out = (float*)d_out;

    // One-time host resource setup (no device memory; same work every call)
    static cudaStream_t s2 = nullptr;
    static cudaEvent_t evFork = nullptr, evJoin = nullptr;
    if (s2 == nullptr) {
        cudaStreamCreateWithFlags(&s2, cudaStreamNonBlocking);
        cudaEventCreateWithFlags(&evFork, cudaEventDisableTiming);
        cudaEventCreateWithFlags(&evJoin, cudaEventDisableTiming);
    }

    // Fork side stream from the (captured) legacy stream
    cudaEventRecord(evFork, 0);
    cudaStreamWaitEvent(s2, evFork, 0);

    // ---- side stream: G2 CSR build + W prep ----
    zero_g2_wprep_kernel<<<ZERO2_BLKS + WPREP_BLKS, 256, 0, s2>>>(W);
    hist_g_kernel<<<(NNZ / 4 + 255) / 256, 256, 0, s2>>>((const int4*)g2d, 1);
    scanA_g_kernel<<<NB2, SCAN_TPB, 0, s2>>>(1);
    scanC_g_kernel<<<NB2, SCAN_TPB, 0, s2>>>(1);
    fill_g_kernel<<<(NNZ / 2 + 255) / 256, 256, 0, s2>>>((const int2*)g2s, (const int2*)g2d, 1);
    cudaEventRecord(evJoin, s2);

    // ---- main (legacy) stream: G1 CSR build + spmm1 ----
    zero_g1_kernel<<<(N_EDGES + 255) / 256, 256>>>();
    hist_g_kernel<<<(NNZ / 4 + 255) / 256, 256>>>((const int4*)g1d, 0);
    scanA_g_kernel<<<NB1, SCAN_TPB>>>(0);
    scanC_g_kernel<<<NB1, SCAN_TPB>>>(0);
    fill_g_kernel<<<(NNZ / 2 + 255) / 256, 256>>>((const int2*)g1s, (const int2*)g1d, 0);
    spmm1_kernel<<<(N_EDGES * 32 + 255) / 256, 256>>>((const float4*)X, degE);

    // join: spmm2 needs g2 CSR + Xe
    cudaStreamWaitEvent(0, evJoin, 0);
    spmm2_kernel<<<(N_NODES * 32 + 255) / 256, 256>>>((const float4*)X0, degV, alpha);

    // tf32 GEMM + residual epilogue (100000 = 6250 * 16 exact)
    gemm_kernel<<<N_NODES / 16, 256>>>(beta, out);
}

// round 9
// speedup vs baseline: 1.0267x; 1.0267x over previous
#include <cuda_runtime.h>
#include <cuda_fp16.h>
#include <cstdint>

#define N_NODES 100000
#define N_EDGES 20000
#define NNZ     800000
#define D       128

// Scan tiling
#define SCAN_TPB   256
#define SCAN_PER   8
#define SCAN_CHUNK (SCAN_TPB * SCAN_PER)                      // 2048
#define NB1 ((N_EDGES + SCAN_CHUNK - 1) / SCAN_CHUNK)         // 10
#define NB2 ((N_NODES + SCAN_CHUNK - 1) / SCAN_CHUNK)         // 49
#define NBT (NB1 + NB2)                                       // 59

// ---------------------------------------------------------------------------
// Device-global scratch (allocation-free rule)
// ---------------------------------------------------------------------------
__device__ __align__(16) uint2 g_XeH[N_EDGES * 32];  // Xe in fp16 (2x half2 per lane), 5.12 MB
__device__ __align__(16) float g_Xv[N_NODES * D];    // 51.2 MB (Xi)
__device__ __align__(16) float2 g_Wp[64 * 128];      // packed tf32 B fragments, 64 KB

__device__ int g1_cnt[N_EDGES];
__device__ int g1_off[N_EDGES + 1];
__device__ int g1_cur[N_EDGES];
__device__ int g1_idx[NNZ];
__device__ int g2_cnt[N_NODES];
__device__ int g2_off[N_NODES + 1];
__device__ int g2_cur[N_NODES];
__device__ int g2_idx[NNZ];

__device__ int g_thr_excl[NBT * SCAN_TPB];
__device__ int g_blk_sum[NBT];

// ---------------------------------------------------------------------------
// bit-cast helpers (register renames; no named intrinsics exist for these)
// ---------------------------------------------------------------------------
__device__ __forceinline__ uint32_t h2_to_u32(__half2 h) {
    return *reinterpret_cast<uint32_t*>(&h);
}
__device__ __forceinline__ __half2 u32_to_h2(uint32_t u) {
    return *reinterpret_cast<__half2*>(&u);
}

__device__ __forceinline__ uint32_t f2tf32(float f) {
    uint32_t r;
    asm("cvt.rna.tf32.f32 %0, %1;" : "=r"(r) : "f"(f));
    return r;
}

// ---------------------------------------------------------------------------
// Merged: zero counters (blocks 0..390) + W prep (blocks 391..422)
// ---------------------------------------------------------------------------
#define ZERO_BLKS ((N_NODES + 255) / 256)        // 391
#define WPREP_BLKS 32

__global__ void zero_wprep_kernel(const float* __restrict__ W) {
    if (blockIdx.x < ZERO_BLKS) {
        int i = blockIdx.x * blockDim.x + threadIdx.x;
        if (i < N_EDGES) g1_cnt[i] = 0;
        if (i < N_NODES) g2_cnt[i] = 0;
    } else {
        int p = (blockIdx.x - ZERO_BLKS) * blockDim.x + threadIdx.x;  // 8192 total
        if (p < 64 * 128) {
            int n = p & 127;
            int tig = (p >> 7) & 3;
            int kk = p >> 9;
            float w0 = __ldg(W + n * 128 + kk * 8 + tig);
            float w1 = __ldg(W + n * 128 + kk * 8 + tig + 4);
            float2 o;
            o.x = __uint_as_float(f2tf32(w0));
            o.y = __uint_as_float(f2tf32(w1));
            g_Wp[p] = o;
        }
    }
}

// ---------------------------------------------------------------------------
// Histogram, both graphs (int4-vectorized: 4 nnz per thread)
// ---------------------------------------------------------------------------
__global__ void hist_kernel(const int4* __restrict__ g1d4,
                            const int4* __restrict__ g2d4) {
    int i = blockIdx.x * blockDim.x + threadIdx.x;
    if (i >= NNZ / 4) return;
    int4 d1 = __ldg(g1d4 + i);
    atomicAdd(&g1_cnt[d1.x], 1);
    atomicAdd(&g1_cnt[d1.y], 1);
    atomicAdd(&g1_cnt[d1.z], 1);
    atomicAdd(&g1_cnt[d1.w], 1);
    int4 d2 = __ldg(g2d4 + i);
    atomicAdd(&g2_cnt[d2.x], 1);
    atomicAdd(&g2_cnt[d2.y], 1);
    atomicAdd(&g2_cnt[d2.z], 1);
    atomicAdd(&g2_cnt[d2.w], 1);
}

// Phase A: per-block partial scan. Blocks [0,NB1) cover g1_cnt, [NB1,NBT) g2_cnt.
__global__ void scanA_kernel() {
    const int bid = blockIdx.x;
    const int t = threadIdx.x;
    const int* cnt; int n, lbase;
    if (bid < NB1) { cnt = g1_cnt; n = N_EDGES; lbase = bid * SCAN_CHUNK; }
    else           { cnt = g2_cnt; n = N_NODES; lbase = (bid - NB1) * SCAN_CHUNK; }

    int s = 0;
    const int i0 = lbase + t * SCAN_PER;
#pragma unroll
    for (int k = 0; k < SCAN_PER; k++) {
        int i = i0 + k;
        s += (i < n) ? cnt[i] : 0;
    }

    const int lane = t & 31, wid = t >> 5;
    int v = s;
#pragma unroll
    for (int o = 1; o < 32; o <<= 1) {
        int u = __shfl_up_sync(0xffffffffu, v, o);
        if (lane >= o) v += u;
    }
    __shared__ int ws[8];
    if (lane == 31) ws[wid] = v;
    __syncthreads();
    if (t < 8) {
        int w = ws[t];
#pragma unroll
        for (int o = 1; o < 8; o <<= 1) {
            int u = __shfl_up_sync(0xffu, w, o);
            if (t >= o) w += u;
        }
        ws[t] = w;
    }
    __syncthreads();

    int excl = v - s + (wid ? ws[wid - 1] : 0);
    g_thr_excl[bid * SCAN_TPB + t] = excl;
    if (t == SCAN_TPB - 1) g_blk_sum[bid] = excl + s;
}

// Phase C (fused B): every block redundantly scans the 59 block sums in smem.
__global__ void scanC_kernel() {
    __shared__ int be[NBT];
    __shared__ int wtot;
    const int bid = blockIdx.x;
    const int t = threadIdx.x;

    if (t < 64) {
        int v = (t < NBT) ? g_blk_sum[t] : 0;
        const int lane = t & 31;
        int s = v;
#pragma unroll
        for (int o = 1; o < 32; o <<= 1) {
            int u = __shfl_up_sync(0xffffffffu, s, o);
            if (lane >= o) s += u;
        }
        if (t == 31) wtot = s;
        if (t < NBT) be[t] = s - v;   // warp-local exclusive
    }
    __syncthreads();
    if (t >= 32 && t < 64 && t < NBT) be[t] += wtot;   // add warp0 total
    __syncthreads();
    if (t < NBT && t >= NB1) be[t] -= NNZ;             // g2 segment rebase
    __syncthreads();

    const int* cnt; int* off; int* cur; int n, lbase;
    if (bid < NB1) { cnt = g1_cnt; off = g1_off; cur = g1_cur; n = N_EDGES; lbase = bid * SCAN_CHUNK; }
    else           { cnt = g2_cnt; off = g2_off; cur = g2_cur; n = N_NODES; lbase = (bid - NB1) * SCAN_CHUNK; }

    int base = be[bid] + g_thr_excl[bid * SCAN_TPB + t];
    const int i0 = lbase + t * SCAN_PER;
#pragma unroll
    for (int k = 0; k < SCAN_PER; k++) {
        int i = i0 + k;
        if (i < n) {
            off[i] = base;
            cur[i] = base;
            base += cnt[i];
        }
    }
    if (bid == 0 && t == 0) {
        g1_off[N_EDGES] = NNZ;
        g2_off[N_NODES] = NNZ;
    }
}

// Fill, both graphs (int2-vectorized: 2 nnz per thread)
__global__ void fill_kernel(const int2* __restrict__ g1s2, const int2* __restrict__ g1d2,
                            const int2* __restrict__ g2s2, const int2* __restrict__ g2d2) {
    int i = blockIdx.x * blockDim.x + threadIdx.x;
    if (i >= NNZ / 2) return;
    int2 s1 = __ldg(g1s2 + i);
    int2 d1 = __ldg(g1d2 + i);
    int p0 = atomicAdd(&g1_cur[d1.x], 1);
    g1_idx[p0] = s1.x;
    int p1 = atomicAdd(&g1_cur[d1.y], 1);
    g1_idx[p1] = s1.y;
    int2 s2 = __ldg(g2s2 + i);
    int2 d2 = __ldg(g2d2 + i);
    int q0 = atomicAdd(&g2_cur[d2.x], 1);
    g2_idx[q0] = s2.x;
    int q1 = atomicAdd(&g2_cur[d2.y], 1);
    g2_idx[q1] = s2.y;
}

// ---------------------------------------------------------------------------
// SpMM 1: XeH[e] = fp16( degE[e] * sum_{s in csr1[e]} X[s] )   (warp per edge)
// ---------------------------------------------------------------------------
__global__ void spmm1_kernel(const float4* __restrict__ X4,
                             const float* __restrict__ degE) {
    int e = (blockIdx.x * blockDim.x + threadIdx.x) >> 5;
    if (e >= N_EDGES) return;
    int lane = threadIdx.x & 31;
    int beg = g1_off[e], end = g1_off[e + 1];

    float4 acc = make_float4(0.f, 0.f, 0.f, 0.f);
    int j = beg;
    for (; j + 4 <= end; j += 4) {
        int s0 = g1_idx[j], s1 = g1_idx[j + 1], s2 = g1_idx[j + 2], s3 = g1_idx[j + 3];
        float4 v0 = __ldg(X4 + s0 * 32 + lane);
        float4 v1 = __ldg(X4 + s1 * 32 + lane);
        float4 v2 = __ldg(X4 + s2 * 32 + lane);
        float4 v3 = __ldg(X4 + s3 * 32 + lane);
        acc.x += (v0.x + v1.x) + (v2.x + v3.x);
        acc.y += (v0.y + v1.y) + (v2.y + v3.y);
        acc.z += (v0.z + v1.z) + (v2.z + v3.z);
        acc.w += (v0.w + v1.w) + (v2.w + v3.w);
    }
    for (; j < end; j++) {
        int s = g1_idx[j];
        float4 v = __ldg(X4 + s * 32 + lane);
        acc.x += v.x; acc.y += v.y; acc.z += v.z; acc.w += v.w;
    }
    float de = __ldg(degE + e);
    __half2 h0 = __floats2half2_rn(acc.x * de, acc.y * de);
    __half2 h1 = __floats2half2_rn(acc.z * de, acc.w * de);
    uint2 o;
    o.x = h2_to_u32(h0);
    o.y = h2_to_u32(h1);
    g_XeH[e * 32 + lane] = o;
}

// ---------------------------------------------------------------------------
// SpMM 2 + residual: g_Xv[v] = (1-a)*degV[v]*sum_{s in csr2[v]} XeH[s] + a*X0[v]
// fp16 gather (8B/lane), fp32 accumulate                     (warp per node)
// ---------------------------------------------------------------------------
__device__ __forceinline__ void acc_half(float4& acc, uint2 r) {
    float2 f0 = __half22float2(u32_to_h2(r.x));
    float2 f1 = __half22float2(u32_to_h2(r.y));
    acc.x += f0.x; acc.y += f0.y; acc.z += f1.x; acc.w += f1.y;
}

__global__ void spmm2_kernel(const float4* __restrict__ X04,
                             const float* __restrict__ degV,
                             const float* __restrict__ alpha) {
    int v = (blockIdx.x * blockDim.x + threadIdx.x) >> 5;
    if (v >= N_NODES) return;
    int lane = threadIdx.x & 31;
    int beg = g2_off[v], end = g2_off[v + 1];

    float4 acc = make_float4(0.f, 0.f, 0.f, 0.f);
    int j = beg;
    for (; j + 4 <= end; j += 4) {
        int s0 = g2_idx[j], s1 = g2_idx[j + 1], s2 = g2_idx[j + 2], s3 = g2_idx[j + 3];
        uint2 r0 = g_XeH[s0 * 32 + lane];
        uint2 r1 = g_XeH[s1 * 32 + lane];
        uint2 r2 = g_XeH[s2 * 32 + lane];
        uint2 r3 = g_XeH[s3 * 32 + lane];
        acc_half(acc, r0);
        acc_half(acc, r1);
        acc_half(acc, r2);
        acc_half(acc, r3);
    }
    for (; j < end; j++) {
        int s = g2_idx[j];
        acc_half(acc, g_XeH[s * 32 + lane]);
    }
    float a = __ldg(alpha);
    float sc = (1.f - a) * __ldg(degV + v);
    float4 x0 = __ldg(X04 + v * 32 + lane);
    float4 xi;
    xi.x = sc * acc.x + a * x0.x;
    xi.y = sc * acc.y + a * x0.y;
    xi.z = sc * acc.z + a * x0.z;
    xi.w = sc * acc.w + a * x0.w;
    reinterpret_cast<float4*>(g_Xv)[v * 32 + lane] = xi;
}

// ---------------------------------------------------------------------------
// GEMM: out = (1-b)*Xi + b*(Xi @ W^T)   (Xi in g_Xv; exact 16-row tiling)
// ---------------------------------------------------------------------------
#define XI_STRIDE 132

__global__ void __launch_bounds__(256, 2)
gemm_kernel(const float* __restrict__ beta, float* __restrict__ out) {
    __shared__ float Xism[16 * XI_STRIDE];

    const int tid = threadIdx.x;
    const int row0 = blockIdx.x * 16;
    const float bb = __ldg(beta);
    const float omb = 1.f - bb;

    const int warp = tid >> 5, lane = tid & 31;
    const int gid = lane >> 2, tig = lane & 3;
    const int nt0 = warp, nt1 = warp + 8;

    float2 bf0[16], bf1[16];
#pragma unroll
    for (int kk = 0; kk < 16; kk++) {
        bf0[kk] = __ldg(&g_Wp[(kk * 4 + tig) * 128 + nt0 * 8 + gid]);
        bf1[kk] = __ldg(&g_Wp[(kk * 4 + tig) * 128 + nt1 * 8 + gid]);
    }

    const float4* Xv4 = reinterpret_cast<const float4*>(g_Xv);
#pragma unroll
    for (int i = tid; i < 16 * 32; i += 256) {
        int r = i >> 5, c4 = i & 31;
        float4 xi = Xv4[(row0 + r) * 32 + c4];
        *reinterpret_cast<float4*>(&Xism[r * XI_STRIDE + c4 * 4]) = xi;
    }
    __syncthreads();

    float c00 = 0.f, c01 = 0.f, c02 = 0.f, c03 = 0.f;
    float c10 = 0.f, c11 = 0.f, c12 = 0.f, c13 = 0.f;

#pragma unroll
    for (int kk = 0; kk < 16; kk++) {
        int c = kk * 8 + tig;
        uint32_t a0 = f2tf32(Xism[gid * XI_STRIDE + c]);
        uint32_t a1 = f2tf32(Xism[(gid + 8) * XI_STRIDE + c]);
        uint32_t a2 = f2tf32(Xism[gid * XI_STRIDE + c + 4]);
        uint32_t a3 = f2tf32(Xism[(gid + 8) * XI_STRIDE + c + 4]);
        uint32_t b00 = __float_as_uint(bf0[kk].x);
        uint32_t b01 = __float_as_uint(bf0[kk].y);
        uint32_t b10 = __float_as_uint(bf1[kk].x);
        uint32_t b11 = __float_as_uint(bf1[kk].y);
        asm volatile(
            "mma.sync.aligned.m16n8k8.row.col.f32.tf32.tf32.f32 "
            "{%0,%1,%2,%3}, {%4,%5,%6,%7}, {%8,%9}, {%0,%1,%2,%3};"
            : "+f"(c00), "+f"(c01), "+f"(c02), "+f"(c03)
            : "r"(a0), "r"(a1), "r"(a2), "r"(a3), "r"(b00), "r"(b01));
        asm volatile(
            "mma.sync.aligned.m16n8k8.row.col.f32.tf32.tf32.f32 "
            "{%0,%1,%2,%3}, {%4,%5,%6,%7}, {%8,%9}, {%0,%1,%2,%3};"
            : "+f"(c10), "+f"(c11), "+f"(c12), "+f"(c13)
            : "r"(a0), "r"(a1), "r"(a2), "r"(a3), "r"(b10), "r"(b11));
    }

    const int r0 = row0 + gid;
    const int r1 = r0 + 8;
    {
        int col = nt0 * 8 + 2 * tig;
        float xi0 = Xism[gid * XI_STRIDE + col];
        float xi1 = Xism[gid * XI_STRIDE + col + 1];
        *reinterpret_cast<float2*>(out + (long)r0 * 128 + col) =
            make_float2(omb * xi0 + bb * c00, omb * xi1 + bb * c01);
        xi0 = Xism[(gid + 8) * XI_STRIDE + col];
        xi1 = Xism[(gid + 8) * XI_STRIDE + col + 1];
        *reinterpret_cast<float2*>(out + (long)r1 * 128 + col) =
            make_float2(omb * xi0 + bb * c02, omb * xi1 + bb * c03);

        col = nt1 * 8 + 2 * tig;
        xi0 = Xism[gid * XI_STRIDE + col];
        xi1 = Xism[gid * XI_STRIDE + col + 1];
        *reinterpret_cast<float2*>(out + (long)r0 * 128 + col) =
            make_float2(omb * xi0 + bb * c10, omb * xi1 + bb * c11);
        xi0 = Xism[(gid + 8) * XI_STRIDE + col];
        xi1 = Xism[(gid + 8) * XI_STRIDE + col + 1];
        *reinterpret_cast<float2*>(out + (long)r1 * 128 + col) =
            make_float2(omb * xi0 + bb * c12, omb * xi1 + bb * c13);
    }
}

// ---------------------------------------------------------------------------
// kernel_launch — serial (R6 structure; streams were neutral on shared LTS)
// ---------------------------------------------------------------------------
extern "C" void kernel_launch(void* const* d_in, const int* in_sizes, int n_in,
                              void* d_out, int out_size) {
    const float* X     = (const float*)d_in[0];
    const float* X0    = (const float*)d_in[1];
    const float* degE  = (const float*)d_in[2];
    const float* degV  = (const float*)d_in[3];
    const float* alpha = (const float*)d_in[4];
    const float* beta  = (const float*)d_in[5];
    const float* W     = (const float*)d_in[6];
    const int*   g1s   = (const int*)d_in[7];
    const int*   g1d   = (const int*)d_in[8];
    const int*   g2s   = (const int*)d_in[9];
    const int*   g2d   = (const int*)d_in[10];
    float* out = (float*)d_out;

    // zero counters + W prep (merged)
    zero_wprep_kernel<<<ZERO_BLKS + WPREP_BLKS, 256>>>(W);

    // CSR build for both graphs
    hist_kernel<<<(NNZ / 4 + 255) / 256, 256>>>((const int4*)g1d, (const int4*)g2d);
    scanA_kernel<<<NBT, SCAN_TPB>>>();
    scanC_kernel<<<NBT, SCAN_TPB>>>();    // fused B+C
    fill_kernel<<<(NNZ / 2 + 255) / 256, 256>>>((const int2*)g1s, (const int2*)g1d,
                                                (const int2*)g2s, (const int2*)g2d);

    // Gather-sum SpMMs (no atomics); Xe in fp16 halves spmm2 gather bytes
    spmm1_kernel<<<(N_EDGES * 32 + 255) / 256, 256>>>((const float4*)X, degE);
    spmm2_kernel<<<(N_NODES * 32 + 255) / 256, 256>>>((const float4*)X0, degV, alpha);

    // tf32 GEMM + residual epilogue (100000 = 6250 * 16 exact)
    gemm_kernel<<<N_NODES / 16, 256>>>(beta, out);
}